// round 1
// baseline (speedup 1.0000x reference)
#include <cuda_runtime.h>
#include <cuda_bf16.h>
#include <cstdint>
#include <math.h>

// Problem constants
#define BB 32768
#define KK 8192
#define DD 384
#define CSPLIT 4
#define JBLOCKS 256

constexpr float INV_T = 1.0f / 0.07f;

// GEMM tiling
#define BM 128
#define BN 128
#define BK 128
constexpr int A_UNITS = DD / 8;          // 48 16B-units per A row
constexpr int B_UNITS = BK / 8;          // 16 16B-units per B row
constexpr int A_BYTES = BM * DD * 2;     // 98304
constexpr int B_BUF_BYTES = BN * BK * 2; // 32768
constexpr int SMEM_TOTAL = A_BYTES + 2 * B_BUF_BYTES; // 163840

// Scratch (device globals: no allocation allowed)
__device__ __nv_bfloat16 g_feat[BB * DD];
__device__ __nv_bfloat16 g_cent[KK * DD];
__device__ float g_rowmax[BB];
__device__ int   g_rowarg[BB];
__device__ float g_centpart[CSPLIT * KK];
__device__ float g_jpart[JBLOCKS];

__device__ __forceinline__ uint32_t smem_addr(const void* p) {
    return (uint32_t)__cvta_generic_to_shared(p);
}
__device__ __forceinline__ void cp16(void* dst, const void* src) {
    asm volatile("cp.async.cg.shared.global [%0], [%1], 16;\n"
                 :: "r"(smem_addr(dst)), "l"(src));
}
__device__ __forceinline__ void cp_commit() {
    asm volatile("cp.async.commit_group;\n" ::);
}

// ---------------------------------------------------------------------------
// Normalize centroids (fp32) -> bf16
// ---------------------------------------------------------------------------
__global__ void k_normalize(const float* __restrict__ cent) {
    __shared__ float red[4];
    int row = blockIdx.x, t = threadIdx.x; // 128 threads
    const float* src = cent + row * DD;
    float v0 = src[t], v1 = src[t + 128], v2 = src[t + 256];
    float s = v0 * v0 + v1 * v1 + v2 * v2;
#pragma unroll
    for (int o = 16; o > 0; o >>= 1) s += __shfl_xor_sync(0xffffffffu, s, o);
    if ((t & 31) == 0) red[t >> 5] = s;
    __syncthreads();
    float tot = red[0] + red[1] + red[2] + red[3];
    float inv = 1.0f / fmaxf(sqrtf(tot), 1e-12f);
    __nv_bfloat16* dst = g_cent + row * DD;
    dst[t]       = __float2bfloat16(v0 * inv);
    dst[t + 128] = __float2bfloat16(v1 * inv);
    dst[t + 256] = __float2bfloat16(v2 * inv);
}

// ---------------------------------------------------------------------------
// Convert features (already L2-normalized fp32) -> bf16
// ---------------------------------------------------------------------------
__global__ void k_convert(const float* __restrict__ f) {
    const int n2 = BB * DD / 2;
    const float2* src = (const float2*)f;
    __nv_bfloat162* dst = (__nv_bfloat162*)g_feat;
    for (int i = blockIdx.x * blockDim.x + threadIdx.x; i < n2;
         i += gridDim.x * blockDim.x) {
        float2 v = src[i];
        dst[i] = __floats2bfloat162_rn(v.x, v.y);
    }
}

// ---------------------------------------------------------------------------
// Fused GEMM (bf16 mma.sync, fp32 accum).
// EPI==0: A = g_feat [BB rows], epilogue = running row max + argmax over all K
// EPI==1: A = g_cent [KK rows], epilogue = running row sum of exp(v/T) over a
//         column split (blockIdx.y) -> g_centpart
// CTA: 128-row stripe, A stripe resident in smem; B streamed in 128x128
// double-buffered chunks (3 chunks of the D=384 contraction per n-tile).
// Warps: 4(M) x 2(N); warp tile 32x64; m16n8k16 frags.
// ---------------------------------------------------------------------------
template <int EPI>
__global__ __launch_bounds__(256, 1) void gemm_kernel() {
    extern __shared__ uint4 smem[];
    uint4* smA = smem;                       // 6144 uint4
    uint4* smB = smem + (A_BYTES / 16);      // 2 x 2048 uint4

    const __nv_bfloat16* A  = (EPI == 0) ? g_feat : g_cent;
    const __nv_bfloat16* Bc = g_cent;

    const int tid  = threadIdx.x;
    const int lane = tid & 31;
    const int wid  = tid >> 5;
    const int wm   = wid >> 1;   // 0..3
    const int wn   = wid & 1;    // 0..1
    const int row0 = blockIdx.x * BM;
    const int col_begin = (EPI == 0) ? 0 : blockIdx.y * (KK / CSPLIT);
    const int NT = (EPI == 0) ? (KK / BN) : ((KK / CSPLIT) / BN);
    const int NC = NT * 3;

    // Load resident A stripe [BM x DD], swizzled (unit ^= row&7)
    for (int i = tid; i < BM * A_UNITS; i += 256) {
        int r = i / A_UNITS, c = i % A_UNITS;
        cp16(&smA[r * A_UNITS + (c ^ (r & 7))],
             A + (size_t)(row0 + r) * DD + c * 8);
    }
    cp_commit();

    // Chunk c covers n-tile c/3, k-chunk (c%3)*128
    auto issueB = [&](int chunk) {
        int nt = chunk / 3, kc = chunk % 3;
        const __nv_bfloat16* src =
            Bc + (size_t)(col_begin + nt * BN) * DD + kc * BK;
        uint4* dst = smB + (chunk & 1) * (B_BUF_BYTES / 16);
        for (int i = tid; i < BN * B_UNITS; i += 256) {
            int r = i / B_UNITS, c = i % B_UNITS;
            cp16(&dst[r * B_UNITS + (c ^ (r & 7))], src + (size_t)r * DD + c * 8);
        }
        cp_commit();
    };

    issueB(0);
    if (NC > 1) issueB(1);

    float acc[2][8][4];
    float bestv[4];
    int   besti[4];
    float rsum[4];
#pragma unroll
    for (int s = 0; s < 4; ++s) {
        bestv[s] = __int_as_float(0xff800000); // -inf
        besti[s] = 0;
        rsum[s]  = 0.0f;
    }

    for (int c = 0; c < NC; ++c) {
        if (c < NC - 1) asm volatile("cp.async.wait_group 1;\n" ::);
        else            asm volatile("cp.async.wait_group 0;\n" ::);
        __syncthreads();

        const int kc = c % 3;
        const uint4* bufB = smB + (c & 1) * (B_BUF_BYTES / 16);

        if (kc == 0) {
#pragma unroll
            for (int mf = 0; mf < 2; ++mf)
#pragma unroll
                for (int nf = 0; nf < 8; ++nf)
#pragma unroll
                    for (int q = 0; q < 4; ++q) acc[mf][nf][q] = 0.0f;
        }

#pragma unroll
        for (int ks = 0; ks < 8; ++ks) {
            uint32_t a[2][4];
#pragma unroll
            for (int mf = 0; mf < 2; ++mf) {
                int r = wm * 32 + mf * 16 + (lane & 15);
                int u = kc * 16 + ks * 2 + (lane >> 4);
                uint32_t addr = smem_addr(&smA[r * A_UNITS + (u ^ (r & 7))]);
                asm volatile(
                    "ldmatrix.sync.aligned.m8n8.x4.shared.b16 {%0,%1,%2,%3}, [%4];\n"
                    : "=r"(a[mf][0]), "=r"(a[mf][1]), "=r"(a[mf][2]), "=r"(a[mf][3])
                    : "r"(addr));
            }
            uint32_t b[4][4];
#pragma unroll
            for (int np = 0; np < 4; ++np) {
                int r = wn * 64 + np * 16 + (lane & 7) + ((lane >> 4) << 3);
                int u = ks * 2 + ((lane >> 3) & 1);
                uint32_t addr = smem_addr(&bufB[r * B_UNITS + (u ^ (r & 7))]);
                asm volatile(
                    "ldmatrix.sync.aligned.m8n8.x4.shared.b16 {%0,%1,%2,%3}, [%4];\n"
                    : "=r"(b[np][0]), "=r"(b[np][1]), "=r"(b[np][2]), "=r"(b[np][3])
                    : "r"(addr));
            }
#pragma unroll
            for (int mf = 0; mf < 2; ++mf)
#pragma unroll
                for (int nf = 0; nf < 8; ++nf) {
                    int np = nf >> 1, h = nf & 1;
                    asm volatile(
                        "mma.sync.aligned.m16n8k16.row.col.f32.bf16.bf16.f32 "
                        "{%0,%1,%2,%3}, {%4,%5,%6,%7}, {%8,%9}, {%0,%1,%2,%3};\n"
                        : "+f"(acc[mf][nf][0]), "+f"(acc[mf][nf][1]),
                          "+f"(acc[mf][nf][2]), "+f"(acc[mf][nf][3])
                        : "r"(a[mf][0]), "r"(a[mf][1]), "r"(a[mf][2]), "r"(a[mf][3]),
                          "r"(b[np][h * 2]), "r"(b[np][h * 2 + 1]));
                }
        }

        if (kc == 2) {
            // full D reduction done for this n-tile -> fold into running epilogue
            int nt = c / 3;
            int colbase = col_begin + nt * BN + wn * 64 + 2 * (lane & 3);
#pragma unroll
            for (int mf = 0; mf < 2; ++mf) {
                int s0 = mf * 2, s1 = mf * 2 + 1;
#pragma unroll
                for (int nf = 0; nf < 8; ++nf) {
                    int col = colbase + nf * 8;
                    if (EPI == 0) {
                        float v0 = acc[mf][nf][0], v1 = acc[mf][nf][1];
                        float v2 = acc[mf][nf][2], v3 = acc[mf][nf][3];
                        if (v0 > bestv[s0]) { bestv[s0] = v0; besti[s0] = col; }
                        if (v1 > bestv[s0]) { bestv[s0] = v1; besti[s0] = col + 1; }
                        if (v2 > bestv[s1]) { bestv[s1] = v2; besti[s1] = col; }
                        if (v3 > bestv[s1]) { bestv[s1] = v3; besti[s1] = col + 1; }
                    } else {
                        rsum[s0] += __expf(acc[mf][nf][0] * INV_T)
                                  + __expf(acc[mf][nf][1] * INV_T);
                        rsum[s1] += __expf(acc[mf][nf][2] * INV_T)
                                  + __expf(acc[mf][nf][3] * INV_T);
                    }
                }
            }
        }

        __syncthreads();
        if (c + 2 < NC) issueB(c + 2);
    }

    // Final reduce: quad shuffle, then combine the 2 N-warps via smem
    float* sred = (float*)smem;               // [2][128]
    int*   sarg = (int*)(sred + 256);         // [2][128]
#pragma unroll
    for (int s = 0; s < 4; ++s) {
        int rl = wm * 32 + (s >> 1) * 16 + (s & 1) * 8 + (lane >> 2);
        if (EPI == 0) {
            float v = bestv[s];
            int ii = besti[s];
#pragma unroll
            for (int o = 1; o <= 2; o <<= 1) {
                float ov = __shfl_xor_sync(0xffffffffu, v, o);
                int oi = __shfl_xor_sync(0xffffffffu, ii, o);
                if (ov > v || (ov == v && oi < ii)) { v = ov; ii = oi; }
            }
            if ((lane & 3) == 0) { sred[wn * 128 + rl] = v; sarg[wn * 128 + rl] = ii; }
        } else {
            float v = rsum[s];
            v += __shfl_xor_sync(0xffffffffu, v, 1);
            v += __shfl_xor_sync(0xffffffffu, v, 2);
            if ((lane & 3) == 0) sred[wn * 128 + rl] = v;
        }
    }
    __syncthreads();
    if (tid < 128) {
        if (EPI == 0) {
            float v0 = sred[tid], v1 = sred[128 + tid];
            int i0 = sarg[tid], i1 = sarg[128 + tid];
            float v = v0; int ii = i0;
            if (v1 > v || (v1 == v && i1 < ii)) { v = v1; ii = i1; }
            g_rowmax[row0 + tid] = v;
            g_rowarg[row0 + tid] = ii;
        } else {
            g_centpart[blockIdx.y * KK + row0 + tid] = sred[tid] + sred[128 + tid];
        }
    }
}

// ---------------------------------------------------------------------------
// Per-sample loss + deterministic two-stage reduction
// ---------------------------------------------------------------------------
__global__ void k_finalj() {
    __shared__ float red[4];
    int i = blockIdx.x * 128 + threadIdx.x;
    float m = g_rowmax[i];
    int a = g_rowarg[i];
    float S = g_centpart[a] + g_centpart[KK + a] + g_centpart[2 * KK + a]
            + g_centpart[3 * KK + a];
    float mt = m * INV_T;
    float J = mt - logf(expf(mt) + S);
    float s = J;
#pragma unroll
    for (int o = 16; o > 0; o >>= 1) s += __shfl_xor_sync(0xffffffffu, s, o);
    if ((threadIdx.x & 31) == 0) red[threadIdx.x >> 5] = s;
    __syncthreads();
    if (threadIdx.x == 0) g_jpart[blockIdx.x] = red[0] + red[1] + red[2] + red[3];
}

__global__ void k_reduce(float* out) {
    __shared__ float red[8];
    int t = threadIdx.x; // 256
    float s = g_jpart[t];
#pragma unroll
    for (int o = 16; o > 0; o >>= 1) s += __shfl_xor_sync(0xffffffffu, s, o);
    if ((t & 31) == 0) red[t >> 5] = s;
    __syncthreads();
    if (t == 0) {
        float tot = 0.0f;
        for (int i = 0; i < 8; ++i) tot += red[i];
        out[0] = -tot / (float)BB;
    }
}

// ---------------------------------------------------------------------------
extern "C" void kernel_launch(void* const* d_in, const int* in_sizes, int n_in,
                              void* d_out, int out_size) {
    const float* feat = (const float*)d_in[0];
    const float* cent = (const float*)d_in[1];
    if (n_in >= 2 && in_sizes[0] == KK * DD && in_sizes[1] == BB * DD) {
        feat = (const float*)d_in[1];
        cent = (const float*)d_in[0];
    }

    cudaFuncSetAttribute((const void*)gemm_kernel<0>,
                         cudaFuncAttributeMaxDynamicSharedMemorySize, SMEM_TOTAL);
    cudaFuncSetAttribute((const void*)gemm_kernel<1>,
                         cudaFuncAttributeMaxDynamicSharedMemorySize, SMEM_TOTAL);

    k_normalize<<<KK, 128>>>(cent);
    k_convert<<<1024, 256>>>(feat);
    gemm_kernel<1><<<dim3(KK / BM, CSPLIT), 256, SMEM_TOTAL>>>(); // centroid-centroid
    gemm_kernel<0><<<dim3(BB / BM, 1), 256, SMEM_TOTAL>>>();      // feature-centroid
    k_finalj<<<JBLOCKS, 128>>>();
    k_reduce<<<1, 256>>>((float*)d_out);
}

// round 3
// speedup vs baseline: 1.2162x; 1.2162x over previous
#include <cuda_runtime.h>
#include <cuda_bf16.h>
#include <cstdint>
#include <math.h>

// Problem constants
#define BB 32768
#define KK 8192
#define DD 384
#define CSPLIT 2
#define JBLOCKS 256

constexpr float INV_T = 1.0f / 0.07f;

// Tiling: CTA tile 128x256, k-chunk 128; 8 warps as 2(M) x 4(N), warp tile 64x64
#define BM 128
#define BN 256
#define BKC 128
constexpr int A_UNITS = DD / 8;              // 48 16B-units per A row
constexpr int A_BYTES = BM * DD * 2;         // 98304 per stripe
constexpr int B_CHUNK = BN * BKC * 2;        // 65536 per chunk
constexpr int CTRL    = A_BYTES + 2 * B_CHUNK;  // 229376
constexpr int SMEM_TOTAL = CTRL + 64;           // 229440

// Pre-swizzled GMEM images (exact byte images of smem tiles)
__device__ uint4 g_featS[BB * DD * 2 / 16];            // 256 stripes x 98304B
__device__ uint4 g_centA[KK * DD * 2 / 16];            // 64 stripes x 98304B
__device__ uint4 g_centB[KK * DD * 2 / 16];            // 96 chunks x 65536B
__device__ float g_rowmax[BB];
__device__ int   g_rowarg[BB];
__device__ float g_centpart[CSPLIT * KK];
__device__ float g_jpart[JBLOCKS];

// ---------------------------------------------------------------------------
__device__ __forceinline__ uint32_t smem_u32(const void* p) {
    return (uint32_t)__cvta_generic_to_shared(p);
}
__device__ __forceinline__ void mbar_init(uint32_t a, uint32_t c) {
    asm volatile("mbarrier.init.shared.b64 [%0], %1;" :: "r"(a), "r"(c) : "memory");
}
__device__ __forceinline__ void mbar_expect(uint32_t a, uint32_t bytes) {
    asm volatile("mbarrier.arrive.expect_tx.shared.b64 _, [%0], %1;"
                 :: "r"(a), "r"(bytes) : "memory");
}
__device__ __forceinline__ void bulk_g2s(uint32_t dst, const void* src,
                                         uint32_t bytes, uint32_t mb) {
    asm volatile(
        "cp.async.bulk.shared::cluster.global.mbarrier::complete_tx::bytes "
        "[%0], [%1], %2, [%3];"
        :: "r"(dst), "l"(src), "r"(bytes), "r"(mb) : "memory");
}
__device__ __forceinline__ void mbar_wait(uint32_t addr, uint32_t parity) {
    asm volatile(
        "{\n\t.reg .pred P;\n\t"
        "WL%=:\n\t"
        "mbarrier.try_wait.parity.acquire.cta.shared::cta.b64 P, [%0], %1, 0x989680;\n\t"
        "@P bra WD%=;\n\t"
        "bra WL%=;\n\t"
        "WD%=:\n\t}"
        :: "r"(addr), "r"(parity) : "memory");
}
#define FENCE_ASYNC() asm volatile("fence.proxy.async.shared::cta;" ::: "memory")

__device__ __forceinline__ void ldsm4(uint32_t (&d)[4], uint32_t addr) {
    asm volatile("ldmatrix.sync.aligned.m8n8.x4.shared.b16 {%0,%1,%2,%3}, [%4];"
                 : "=r"(d[0]), "=r"(d[1]), "=r"(d[2]), "=r"(d[3]) : "r"(addr));
}

// ---------------------------------------------------------------------------
// Prep: features fp32 -> bf16, written as pre-swizzled stripe images.
// Stripe s, row r (0..127), unit u (0..47): dst unit = s*6144 + r*48 + (u^(r&7))
// ---------------------------------------------------------------------------
__global__ void k_prep_feat(const float* __restrict__ feat) {
    const int NU = BB / BM * BM * A_UNITS; // 1572864
    for (int idx = blockIdx.x * blockDim.x + threadIdx.x; idx < NU;
         idx += gridDim.x * blockDim.x) {
        int u = idx % A_UNITS;
        int r = (idx / A_UNITS) % BM;
        int s = idx / (A_UNITS * BM);
        const float4* src =
            (const float4*)(feat + (size_t)(s * BM + r) * DD + u * 8);
        float4 f0 = src[0], f1 = src[1];
        __nv_bfloat162 p0 = __floats2bfloat162_rn(f0.x, f0.y);
        __nv_bfloat162 p1 = __floats2bfloat162_rn(f0.z, f0.w);
        __nv_bfloat162 p2 = __floats2bfloat162_rn(f1.x, f1.y);
        __nv_bfloat162 p3 = __floats2bfloat162_rn(f1.z, f1.w);
        uint4 v;
        v.x = *(uint32_t*)&p0; v.y = *(uint32_t*)&p1;
        v.z = *(uint32_t*)&p2; v.w = *(uint32_t*)&p3;
        g_featS[s * (BM * A_UNITS) + r * A_UNITS + (u ^ (r & 7))] = v;
    }
}

// ---------------------------------------------------------------------------
// Prep: centroids normalize -> bf16, written as BOTH A-stripe images and
// B-chunk images. One block per centroid row, 128 threads.
// B chunk (nt,kc): row rr (0..255), unit uu (0..15): unit index
//   (nt*3+kc)*4096 + rr*16 + (uu^(rr&7))
// ---------------------------------------------------------------------------
__global__ void k_prep_cent(const float* __restrict__ cent) {
    __shared__ float red[4];
    int row = blockIdx.x, t = threadIdx.x;
    const float* src = cent + (size_t)row * DD;
    float v0 = src[t], v1 = src[t + 128], v2 = src[t + 256];
    float s = v0 * v0 + v1 * v1 + v2 * v2;
#pragma unroll
    for (int o = 16; o > 0; o >>= 1) s += __shfl_xor_sync(0xffffffffu, s, o);
    if ((t & 31) == 0) red[t >> 5] = s;
    __syncthreads();
    float inv = 1.0f / fmaxf(sqrtf(red[0] + red[1] + red[2] + red[3]), 1e-12f);

    // unit writer: j in 0..47 (two groups of threads)
    int j = -1;
    if (t < 48) j = t;
    else if (t >= 64 && t < 112) j = t - 64;
    if (j >= 0) {
        const float4* sp = (const float4*)(src + j * 8);
        float4 f0 = sp[0], f1 = sp[1];
        __nv_bfloat162 p0 = __floats2bfloat162_rn(f0.x * inv, f0.y * inv);
        __nv_bfloat162 p1 = __floats2bfloat162_rn(f0.z * inv, f0.w * inv);
        __nv_bfloat162 p2 = __floats2bfloat162_rn(f1.x * inv, f1.y * inv);
        __nv_bfloat162 p3 = __floats2bfloat162_rn(f1.z * inv, f1.w * inv);
        uint4 v;
        v.x = *(uint32_t*)&p0; v.y = *(uint32_t*)&p1;
        v.z = *(uint32_t*)&p2; v.w = *(uint32_t*)&p3;
        if (t < 48) {
            int sA = row >> 7, r = row & 127;
            g_centA[sA * (BM * A_UNITS) + r * A_UNITS + (j ^ (r & 7))] = v;
        } else {
            int nt = row >> 8, rr = row & 255, kc = j >> 4, uu = j & 15;
            g_centB[(size_t)(nt * 3 + kc) * 4096 + rr * 16 + (uu ^ (rr & 7))] = v;
        }
    }
}

// ---------------------------------------------------------------------------
// Fused GEMM: 256 threads, warp grid 2(M) x 4(N), warp tile 64x64.
// A stripe (96KB) + double-buffered B chunks (2x64KB) loaded by single-thread
// cp.async.bulk from pre-swizzled GMEM images -> LSU stays free for ldmatrix.
// EPI==0: A=g_featS, epilogue row max+argmax.  EPI==1: A=g_centA, sum exp(v/T).
// ---------------------------------------------------------------------------
template <int EPI>
__global__ void __launch_bounds__(256, 1) gemm_tc() {
    extern __shared__ char smem[];
    const int tid = threadIdx.x, lane = tid & 31, wid = tid >> 5;
    const int wm = wid >> 2, wn = wid & 3;
    const uint32_t sb = smem_u32(smem);
    const uint32_t mbA = sb + CTRL;

    const int col_begin = (EPI == 0) ? 0 : (int)blockIdx.y * (KK / CSPLIT);
    const int nt0 = col_begin / BN;
    const int NT = (EPI == 0) ? (KK / BN) : (KK / CSPLIT / BN);
    const int NC = NT * 3;
    const int row0 = blockIdx.x * BM;
    const uint4* Asrc = ((EPI == 0) ? g_featS : g_centA)
                      + (size_t)blockIdx.x * (BM * A_UNITS);

    if (tid == 0) {
        mbar_init(mbA, 1);
        mbar_init(mbA + 8, 1);
        mbar_init(mbA + 16, 1);
    }
    __syncthreads();

    auto issueB = [&](int c) {
        int slot = c & 1;
        uint32_t mb = mbA + 8 + slot * 8;
        const uint4* src = g_centB + (size_t)((nt0 + c / 3) * 3 + c % 3) * 4096;
        mbar_expect(mb, B_CHUNK);
        bulk_g2s(sb + A_BYTES + slot * B_CHUNK, src, B_CHUNK, mb);
    };
    if (tid == 0) {
        mbar_expect(mbA, A_BYTES);
        bulk_g2s(sb, Asrc, A_BYTES, mbA);
        issueB(0);
        issueB(1);
    }

    float acc[4][8][4];
    float bestv[8];
    int   besti[8];
    float rsum[8];
#pragma unroll
    for (int s = 0; s < 8; ++s) {
        bestv[s] = __int_as_float(0xff800000);
        besti[s] = 0;
        rsum[s]  = 0.0f;
    }

    // precomputed per-thread ldmatrix row offsets
    uint32_t a_rowoff[4], b_rowoff[4];
#pragma unroll
    for (int mf = 0; mf < 4; ++mf) {
        int r = wm * 64 + mf * 16 + (lane & 15);
        a_rowoff[mf] = (uint32_t)(r * A_UNITS) * 16u + ((uint32_t)(r & 7) << 4 << 16);
        // pack r&7 in high bits? no -- keep simple: store r*A_UNITS*16 and r&7
    }
    // (simplicity: recompute inside; ptxas hoists)

    mbar_wait(mbA, 0);  // A stripe ready

    for (int c = 0; c < NC; ++c) {
        const int slot = c & 1, kc = c % 3, nt = c / 3;
        mbar_wait(mbA + 8 + slot * 8, (uint32_t)((c >> 1) & 1));
        const uint32_t bbase = sb + A_BYTES + slot * B_CHUNK;

        if (kc == 0) {
#pragma unroll
            for (int mf = 0; mf < 4; ++mf)
#pragma unroll
                for (int nf = 0; nf < 8; ++nf)
#pragma unroll
                    for (int q = 0; q < 4; ++q) acc[mf][nf][q] = 0.0f;
        }

#pragma unroll
        for (int ks = 0; ks < 8; ++ks) {
            uint32_t a[4][4], b[4][4];
#pragma unroll
            for (int mf = 0; mf < 4; ++mf) {
                int r = wm * 64 + mf * 16 + (lane & 15);
                int u = kc * 16 + ks * 2 + (lane >> 4);
                ldsm4(a[mf], sb + (uint32_t)(r * A_UNITS + (u ^ (r & 7))) * 16u);
            }
#pragma unroll
            for (int np = 0; np < 4; ++np) {
                int r = wn * 64 + np * 16 + (lane & 7) + ((lane >> 4) << 3);
                int u = ks * 2 + ((lane >> 3) & 1);
                ldsm4(b[np], bbase + (uint32_t)(r * 16 + (u ^ (r & 7))) * 16u);
            }
#pragma unroll
            for (int mf = 0; mf < 4; ++mf)
#pragma unroll
                for (int nf = 0; nf < 8; ++nf) {
                    int np = nf >> 1, h = nf & 1;
                    asm volatile(
                        "mma.sync.aligned.m16n8k16.row.col.f32.bf16.bf16.f32 "
                        "{%0,%1,%2,%3}, {%4,%5,%6,%7}, {%8,%9}, {%0,%1,%2,%3};\n"
                        : "+f"(acc[mf][nf][0]), "+f"(acc[mf][nf][1]),
                          "+f"(acc[mf][nf][2]), "+f"(acc[mf][nf][3])
                        : "r"(a[mf][0]), "r"(a[mf][1]), "r"(a[mf][2]), "r"(a[mf][3]),
                          "r"(b[np][h * 2]), "r"(b[np][h * 2 + 1]));
                }
        }

        if (kc == 2) {
            int cbase = col_begin + nt * BN + wn * 64 + 2 * (lane & 3);
#pragma unroll
            for (int mf = 0; mf < 4; ++mf)
#pragma unroll
                for (int nf = 0; nf < 8; ++nf) {
                    int col = cbase + nf * 8;
                    int s0 = mf * 2, s1 = mf * 2 + 1;
                    if (EPI == 0) {
                        float v0 = acc[mf][nf][0], v1 = acc[mf][nf][1];
                        float v2 = acc[mf][nf][2], v3 = acc[mf][nf][3];
                        if (v0 > bestv[s0]) { bestv[s0] = v0; besti[s0] = col; }
                        if (v1 > bestv[s0]) { bestv[s0] = v1; besti[s0] = col + 1; }
                        if (v2 > bestv[s1]) { bestv[s1] = v2; besti[s1] = col; }
                        if (v3 > bestv[s1]) { bestv[s1] = v3; besti[s1] = col + 1; }
                    } else {
                        rsum[s0] += __expf(acc[mf][nf][0] * INV_T)
                                  + __expf(acc[mf][nf][1] * INV_T);
                        rsum[s1] += __expf(acc[mf][nf][2] * INV_T)
                                  + __expf(acc[mf][nf][3] * INV_T);
                    }
                }
        }

        __syncthreads();  // all consumers done with slot -> safe to refill
        if (tid == 0 && c + 2 < NC) {
            FENCE_ASYNC();
            issueB(c + 2);
        }
    }

    // Final reduce. Rows per thread-slot s: mf=s>>1, half=s&1:
    //   row = wm*64 + mf*16 + (lane>>2) + half*8 ; cols partitioned by (wn, lane&3)
    float* sred = (float*)smem;           // [4][128]
    int*   sarg = (int*)(smem + 2048);    // [4][128]
#pragma unroll
    for (int s = 0; s < 8; ++s) {
        int row = wm * 64 + (s >> 1) * 16 + (lane >> 2) + (s & 1) * 8;
        if (EPI == 0) {
            float v = bestv[s];
            int ii = besti[s];
#pragma unroll
            for (int o = 1; o <= 2; o <<= 1) {
                float ov = __shfl_xor_sync(0xffffffffu, v, o);
                int oi = __shfl_xor_sync(0xffffffffu, ii, o);
                if (ov > v || (ov == v && oi < ii)) { v = ov; ii = oi; }
            }
            if ((lane & 3) == 0) { sred[wn * 128 + row] = v; sarg[wn * 128 + row] = ii; }
        } else {
            float v = rsum[s];
            v += __shfl_xor_sync(0xffffffffu, v, 1);
            v += __shfl_xor_sync(0xffffffffu, v, 2);
            if ((lane & 3) == 0) sred[wn * 128 + row] = v;
        }
    }
    __syncthreads();
    if (tid < 128) {
        if (EPI == 0) {
            float v = sred[tid]; int ii = sarg[tid];
#pragma unroll
            for (int w = 1; w < 4; ++w) {
                float ov = sred[w * 128 + tid]; int oi = sarg[w * 128 + tid];
                if (ov > v || (ov == v && oi < ii)) { v = ov; ii = oi; }
            }
            g_rowmax[row0 + tid] = v;
            g_rowarg[row0 + tid] = ii;
        } else {
            g_centpart[(size_t)blockIdx.y * KK + row0 + tid] =
                sred[tid] + sred[128 + tid] + sred[256 + tid] + sred[384 + tid];
        }
    }
}

// ---------------------------------------------------------------------------
// Per-sample loss + deterministic two-stage reduction
// ---------------------------------------------------------------------------
__global__ void k_finalj() {
    __shared__ float red[4];
    int i = blockIdx.x * 128 + threadIdx.x;
    float m = g_rowmax[i];
    int a = g_rowarg[i];
    float S = g_centpart[a] + g_centpart[KK + a];
    float mt = m * INV_T;
    float J = mt - logf(expf(mt) + S);
    float s = J;
#pragma unroll
    for (int o = 16; o > 0; o >>= 1) s += __shfl_xor_sync(0xffffffffu, s, o);
    if ((threadIdx.x & 31) == 0) red[threadIdx.x >> 5] = s;
    __syncthreads();
    if (threadIdx.x == 0) g_jpart[blockIdx.x] = red[0] + red[1] + red[2] + red[3];
}

__global__ void k_reduce(float* out) {
    __shared__ float red[8];
    int t = threadIdx.x; // 256
    float s = g_jpart[t];
#pragma unroll
    for (int o = 16; o > 0; o >>= 1) s += __shfl_xor_sync(0xffffffffu, s, o);
    if ((t & 31) == 0) red[t >> 5] = s;
    __syncthreads();
    if (t == 0) {
        float tot = 0.0f;
        for (int i = 0; i < 8; ++i) tot += red[i];
        out[0] = -tot / (float)BB;
    }
}

// ---------------------------------------------------------------------------
extern "C" void kernel_launch(void* const* d_in, const int* in_sizes, int n_in,
                              void* d_out, int out_size) {
    const float* feat = (const float*)d_in[0];
    const float* cent = (const float*)d_in[1];
    if (n_in >= 2 && in_sizes[0] == KK * DD && in_sizes[1] == BB * DD) {
        feat = (const float*)d_in[1];
        cent = (const float*)d_in[0];
    }

    cudaFuncSetAttribute((const void*)gemm_tc<0>,
                         cudaFuncAttributeMaxDynamicSharedMemorySize, SMEM_TOTAL);
    cudaFuncSetAttribute((const void*)gemm_tc<1>,
                         cudaFuncAttributeMaxDynamicSharedMemorySize, SMEM_TOTAL);

    k_prep_feat<<<3072, 256>>>(feat);
    k_prep_cent<<<KK, 128>>>(cent);
    gemm_tc<1><<<dim3(KK / BM, CSPLIT), 256, SMEM_TOTAL>>>(); // centroid-centroid
    gemm_tc<0><<<dim3(BB / BM, 1), 256, SMEM_TOTAL>>>();      // feature-centroid
    k_finalj<<<JBLOCKS, 128>>>();
    k_reduce<<<1, 256>>>((float*)d_out);
}

// round 4
// speedup vs baseline: 1.3096x; 1.0767x over previous
#include <cuda_runtime.h>
#include <cuda_bf16.h>
#include <cstdint>
#include <math.h>

// Problem constants
#define BB 32768
#define KK 8192
#define DD 384
#define JBLOCKS 256

constexpr float INV_T = 1.0f / 0.07f;

// Tiling: CTA tile 128x256, k-chunk 128; 8 warps as 2(M) x 4(N), warp tile 64x64
#define BM 128
#define BN 256
#define BKC 128
constexpr int A_UNITS = DD / 8;              // 48 16B-units per A row
constexpr int A_BYTES = BM * DD * 2;         // 98304 per stripe
constexpr int B_CHUNK = BN * BKC * 2;        // 65536 per chunk
constexpr int CTRL    = A_BYTES + 2 * B_CHUNK;  // 229376
constexpr int SMEM_TOTAL = CTRL + 64;           // 229440

// Grid: 640 uniform CTAs, each does 16 n-tiles (48 chunks).
//   bid < 512 : GEMM1 (features x centroids), stripe=bid>>1, k-half=bid&1
//   bid >= 512: GEMM2 (centroids x centroids), stripe=(bid-512)&63, half=(bid-512)>>6
#define NTILES 16
#define NCHUNK (NTILES * 3)

// Pre-swizzled GMEM images (exact byte images of smem tiles)
__device__ uint4 g_featS[BB * DD * 2 / 16];
__device__ uint4 g_centA[KK * DD * 2 / 16];
__device__ uint4 g_centB[KK * DD * 2 / 16];
__device__ float g_rowmax[2 * BB];
__device__ int   g_rowarg[2 * BB];
__device__ float g_centpart[2 * KK];
__device__ float g_jpart[JBLOCKS];

// ---------------------------------------------------------------------------
__device__ __forceinline__ uint32_t smem_u32(const void* p) {
    return (uint32_t)__cvta_generic_to_shared(p);
}
__device__ __forceinline__ void mbar_init(uint32_t a, uint32_t c) {
    asm volatile("mbarrier.init.shared.b64 [%0], %1;" :: "r"(a), "r"(c) : "memory");
}
__device__ __forceinline__ void mbar_expect(uint32_t a, uint32_t bytes) {
    asm volatile("mbarrier.arrive.expect_tx.shared.b64 _, [%0], %1;"
                 :: "r"(a), "r"(bytes) : "memory");
}
__device__ __forceinline__ void mbar_arrive(uint32_t a) {
    asm volatile("mbarrier.arrive.release.cta.shared::cta.b64 _, [%0];"
                 :: "r"(a) : "memory");
}
__device__ __forceinline__ void bulk_g2s(uint32_t dst, const void* src,
                                         uint32_t bytes, uint32_t mb) {
    asm volatile(
        "cp.async.bulk.shared::cluster.global.mbarrier::complete_tx::bytes "
        "[%0], [%1], %2, [%3];"
        :: "r"(dst), "l"(src), "r"(bytes), "r"(mb) : "memory");
}
__device__ __forceinline__ void mbar_wait(uint32_t addr, uint32_t parity) {
    asm volatile(
        "{\n\t.reg .pred P;\n\t"
        "WL%=:\n\t"
        "mbarrier.try_wait.parity.acquire.cta.shared::cta.b64 P, [%0], %1, 0x989680;\n\t"
        "@P bra WD%=;\n\t"
        "bra WL%=;\n\t"
        "WD%=:\n\t}"
        :: "r"(addr), "r"(parity) : "memory");
}
#define FENCE_ASYNC() asm volatile("fence.proxy.async.shared::cta;" ::: "memory")

__device__ __forceinline__ void ldsm4(uint32_t (&d)[4], uint32_t addr) {
    asm volatile("ldmatrix.sync.aligned.m8n8.x4.shared.b16 {%0,%1,%2,%3}, [%4];"
                 : "=r"(d[0]), "=r"(d[1]), "=r"(d[2]), "=r"(d[3]) : "r"(addr));
}

// ---------------------------------------------------------------------------
// Prep: features fp32 -> bf16 pre-swizzled stripe images.
// ---------------------------------------------------------------------------
__global__ void k_prep_feat(const float* __restrict__ feat) {
    const int NU = BB * A_UNITS;
    for (int idx = blockIdx.x * blockDim.x + threadIdx.x; idx < NU;
         idx += gridDim.x * blockDim.x) {
        int u = idx % A_UNITS;
        int r = (idx / A_UNITS) % BM;
        int s = idx / (A_UNITS * BM);
        const float4* src =
            (const float4*)(feat + (size_t)(s * BM + r) * DD + u * 8);
        float4 f0 = src[0], f1 = src[1];
        __nv_bfloat162 p0 = __floats2bfloat162_rn(f0.x, f0.y);
        __nv_bfloat162 p1 = __floats2bfloat162_rn(f0.z, f0.w);
        __nv_bfloat162 p2 = __floats2bfloat162_rn(f1.x, f1.y);
        __nv_bfloat162 p3 = __floats2bfloat162_rn(f1.z, f1.w);
        uint4 v;
        v.x = *(uint32_t*)&p0; v.y = *(uint32_t*)&p1;
        v.z = *(uint32_t*)&p2; v.w = *(uint32_t*)&p3;
        g_featS[s * (BM * A_UNITS) + r * A_UNITS + (u ^ (r & 7))] = v;
    }
}

// ---------------------------------------------------------------------------
// Prep: centroids normalize -> bf16 as A-stripe and B-chunk images.
// ---------------------------------------------------------------------------
__global__ void k_prep_cent(const float* __restrict__ cent) {
    __shared__ float red[4];
    int row = blockIdx.x, t = threadIdx.x;
    const float* src = cent + (size_t)row * DD;
    float v0 = src[t], v1 = src[t + 128], v2 = src[t + 256];
    float s = v0 * v0 + v1 * v1 + v2 * v2;
#pragma unroll
    for (int o = 16; o > 0; o >>= 1) s += __shfl_xor_sync(0xffffffffu, s, o);
    if ((t & 31) == 0) red[t >> 5] = s;
    __syncthreads();
    float inv = 1.0f / fmaxf(sqrtf(red[0] + red[1] + red[2] + red[3]), 1e-12f);

    int j = -1;
    if (t < 48) j = t;
    else if (t >= 64 && t < 112) j = t - 64;
    if (j >= 0) {
        const float4* sp = (const float4*)(src + j * 8);
        float4 f0 = sp[0], f1 = sp[1];
        __nv_bfloat162 p0 = __floats2bfloat162_rn(f0.x * inv, f0.y * inv);
        __nv_bfloat162 p1 = __floats2bfloat162_rn(f0.z * inv, f0.w * inv);
        __nv_bfloat162 p2 = __floats2bfloat162_rn(f1.x * inv, f1.y * inv);
        __nv_bfloat162 p3 = __floats2bfloat162_rn(f1.z * inv, f1.w * inv);
        uint4 v;
        v.x = *(uint32_t*)&p0; v.y = *(uint32_t*)&p1;
        v.z = *(uint32_t*)&p2; v.w = *(uint32_t*)&p3;
        if (t < 48) {
            int sA = row >> 7, r = row & 127;
            g_centA[sA * (BM * A_UNITS) + r * A_UNITS + (j ^ (r & 7))] = v;
        } else {
            int nt = row >> 8, rr = row & 255, kc = j >> 4, uu = j & 15;
            g_centB[(size_t)(nt * 3 + kc) * 4096 + rr * 16 + (uu ^ (rr & 7))] = v;
        }
    }
}

// ---------------------------------------------------------------------------
// Fused GEMM, 640 uniform CTAs (both GEMMs, both splits) in one launch.
// No __syncthreads in the mainloop: full[slot] mbarriers gate data arrival
// (tx-count), empty[slot] mbarriers (count=8, one arrive per warp) gate
// buffer reuse; only thread 0 ever waits on empty before re-issuing bulk.
// ---------------------------------------------------------------------------
__global__ void __launch_bounds__(256, 1) gemm_all() {
    extern __shared__ char smem[];
    const int tid = threadIdx.x, lane = tid & 31, wid = tid >> 5;
    const int wm = wid >> 2, wn = wid & 3;
    const uint32_t sb = smem_u32(smem);
    const uint32_t mbA = sb + CTRL;          // A full
    const uint32_t mbF = sb + CTRL + 8;      // B full[2]
    const uint32_t mbE = sb + CTRL + 24;     // B empty[2]

    const int bid = blockIdx.x;
    int epi, stripe, split;
    if (bid < 512) { epi = 0; stripe = bid >> 1; split = bid & 1; }
    else           { epi = 1; stripe = (bid - 512) & 63; split = (bid - 512) >> 6; }
    const int row0 = stripe * BM;
    const int col_begin = split * (KK / 2);
    const int nt0 = col_begin / BN;
    const uint4* Asrc = (epi == 0 ? g_featS : g_centA)
                      + (size_t)stripe * (BM * A_UNITS);

    if (tid == 0) {
        mbar_init(mbA, 1);
        mbar_init(mbF, 1);      mbar_init(mbF + 8, 1);
        mbar_init(mbE, 8);      mbar_init(mbE + 8, 8);
    }
    __syncthreads();

    auto issueB = [&](int c) {
        int slot = c & 1;
        uint32_t mb = mbF + slot * 8;
        const uint4* src = g_centB + (size_t)((nt0 + c / 3) * 3 + c % 3) * 4096;
        mbar_expect(mb, B_CHUNK);
        bulk_g2s(sb + A_BYTES + slot * B_CHUNK, src, B_CHUNK, mb);
    };
    if (tid == 0) {
        mbar_expect(mbA, A_BYTES);
        bulk_g2s(sb, Asrc, A_BYTES, mbA);
        issueB(0);
        issueB(1);
    }

    float acc[4][8][4];
    float bestv[8];
    int   besti[8];
    float rsum[8];
#pragma unroll
    for (int s = 0; s < 8; ++s) {
        bestv[s] = __int_as_float(0xff800000);
        besti[s] = 0;
        rsum[s]  = 0.0f;
    }

    mbar_wait(mbA, 0);  // A stripe resident

    for (int c = 0; c < NCHUNK; ++c) {
        const int slot = c & 1, kc = c % 3, nt = c / 3;
        const uint32_t par = (uint32_t)((c >> 1) & 1);
        mbar_wait(mbF + slot * 8, par);
        const uint32_t bbase = sb + A_BYTES + slot * B_CHUNK;

        if (kc == 0) {
#pragma unroll
            for (int mf = 0; mf < 4; ++mf)
#pragma unroll
                for (int nf = 0; nf < 8; ++nf)
#pragma unroll
                    for (int q = 0; q < 4; ++q) acc[mf][nf][q] = 0.0f;
        }

#pragma unroll
        for (int ks = 0; ks < 8; ++ks) {
            uint32_t a[4][4], b[4][4];
#pragma unroll
            for (int mf = 0; mf < 4; ++mf) {
                int r = wm * 64 + mf * 16 + (lane & 15);
                int u = kc * 16 + ks * 2 + (lane >> 4);
                ldsm4(a[mf], sb + (uint32_t)(r * A_UNITS + (u ^ (r & 7))) * 16u);
            }
#pragma unroll
            for (int np = 0; np < 4; ++np) {
                int r = wn * 64 + np * 16 + (lane & 7) + ((lane >> 4) << 3);
                int u = ks * 2 + ((lane >> 3) & 1);
                ldsm4(b[np], bbase + (uint32_t)(r * 16 + (u ^ (r & 7))) * 16u);
            }
#pragma unroll
            for (int mf = 0; mf < 4; ++mf)
#pragma unroll
                for (int nf = 0; nf < 8; ++nf) {
                    int np = nf >> 1, h = nf & 1;
                    asm volatile(
                        "mma.sync.aligned.m16n8k16.row.col.f32.bf16.bf16.f32 "
                        "{%0,%1,%2,%3}, {%4,%5,%6,%7}, {%8,%9}, {%0,%1,%2,%3};\n"
                        : "+f"(acc[mf][nf][0]), "+f"(acc[mf][nf][1]),
                          "+f"(acc[mf][nf][2]), "+f"(acc[mf][nf][3])
                        : "r"(a[mf][0]), "r"(a[mf][1]), "r"(a[mf][2]), "r"(a[mf][3]),
                          "r"(b[np][h * 2]), "r"(b[np][h * 2 + 1]));
                }
        }

        // this warp is done reading slot's smem
        if (lane == 0) mbar_arrive(mbE + slot * 8);
        // producer: refill slot once all 8 warps have released it
        if (tid == 0 && c + 2 < NCHUNK) {
            mbar_wait(mbE + slot * 8, par);
            FENCE_ASYNC();
            issueB(c + 2);
        }

        if (kc == 2) {
            int cbase = col_begin + nt * BN + wn * 64 + 2 * (lane & 3);
#pragma unroll
            for (int mf = 0; mf < 4; ++mf)
#pragma unroll
                for (int nf = 0; nf < 8; ++nf) {
                    int col = cbase + nf * 8;
                    int s0 = mf * 2, s1 = mf * 2 + 1;
                    if (epi == 0) {
                        float v0 = acc[mf][nf][0], v1 = acc[mf][nf][1];
                        float v2 = acc[mf][nf][2], v3 = acc[mf][nf][3];
                        if (v0 > bestv[s0]) { bestv[s0] = v0; besti[s0] = col; }
                        if (v1 > bestv[s0]) { bestv[s0] = v1; besti[s0] = col + 1; }
                        if (v2 > bestv[s1]) { bestv[s1] = v2; besti[s1] = col; }
                        if (v3 > bestv[s1]) { bestv[s1] = v3; besti[s1] = col + 1; }
                    } else {
                        rsum[s0] += __expf(acc[mf][nf][0] * INV_T)
                                  + __expf(acc[mf][nf][1] * INV_T);
                        rsum[s1] += __expf(acc[mf][nf][2] * INV_T)
                                  + __expf(acc[mf][nf][3] * INV_T);
                    }
                }
        }
    }

    __syncthreads();  // all warps done with smem tiles -> reuse for reduction
    float* sred = (float*)smem;           // [4][128]
    int*   sarg = (int*)(smem + 2048);    // [4][128]
#pragma unroll
    for (int s = 0; s < 8; ++s) {
        int row = wm * 64 + (s >> 1) * 16 + (lane >> 2) + (s & 1) * 8;
        if (epi == 0) {
            float v = bestv[s];
            int ii = besti[s];
#pragma unroll
            for (int o = 1; o <= 2; o <<= 1) {
                float ov = __shfl_xor_sync(0xffffffffu, v, o);
                int oi = __shfl_xor_sync(0xffffffffu, ii, o);
                if (ov > v || (ov == v && oi < ii)) { v = ov; ii = oi; }
            }
            if ((lane & 3) == 0) { sred[wn * 128 + row] = v; sarg[wn * 128 + row] = ii; }
        } else {
            float v = rsum[s];
            v += __shfl_xor_sync(0xffffffffu, v, 1);
            v += __shfl_xor_sync(0xffffffffu, v, 2);
            if ((lane & 3) == 0) sred[wn * 128 + row] = v;
        }
    }
    __syncthreads();
    if (tid < 128) {
        if (epi == 0) {
            float v = sred[tid]; int ii = sarg[tid];
#pragma unroll
            for (int w = 1; w < 4; ++w) {
                float ov = sred[w * 128 + tid]; int oi = sarg[w * 128 + tid];
                if (ov > v || (ov == v && oi < ii)) { v = ov; ii = oi; }
            }
            g_rowmax[split * BB + row0 + tid] = v;
            g_rowarg[split * BB + row0 + tid] = ii;
        } else {
            g_centpart[split * KK + row0 + tid] =
                sred[tid] + sred[128 + tid] + sred[256 + tid] + sred[384 + tid];
        }
    }
}

// ---------------------------------------------------------------------------
// Per-sample loss: merge k-split halves, add centroid sums, reduce.
// ---------------------------------------------------------------------------
__global__ void k_finalj() {
    __shared__ float red[4];
    int i = blockIdx.x * 128 + threadIdx.x;
    float m = g_rowmax[i];
    int a = g_rowarg[i];
    float m1 = g_rowmax[BB + i];
    int a1 = g_rowarg[BB + i];
    if (m1 > m) { m = m1; a = a1; }   // tie -> half 0 (lower index) wins
    float S = g_centpart[a] + g_centpart[KK + a];
    float mt = m * INV_T;
    float J = mt - logf(expf(mt) + S);
    float s = J;
#pragma unroll
    for (int o = 16; o > 0; o >>= 1) s += __shfl_xor_sync(0xffffffffu, s, o);
    if ((threadIdx.x & 31) == 0) red[threadIdx.x >> 5] = s;
    __syncthreads();
    if (threadIdx.x == 0) g_jpart[blockIdx.x] = red[0] + red[1] + red[2] + red[3];
}

__global__ void k_reduce(float* out) {
    __shared__ float red[8];
    int t = threadIdx.x; // 256
    float s = g_jpart[t];
#pragma unroll
    for (int o = 16; o > 0; o >>= 1) s += __shfl_xor_sync(0xffffffffu, s, o);
    if ((t & 31) == 0) red[t >> 5] = s;
    __syncthreads();
    if (t == 0) {
        float tot = 0.0f;
        for (int i = 0; i < 8; ++i) tot += red[i];
        out[0] = -tot / (float)BB;
    }
}

// ---------------------------------------------------------------------------
extern "C" void kernel_launch(void* const* d_in, const int* in_sizes, int n_in,
                              void* d_out, int out_size) {
    const float* feat = (const float*)d_in[0];
    const float* cent = (const float*)d_in[1];
    if (n_in >= 2 && in_sizes[0] == KK * DD && in_sizes[1] == BB * DD) {
        feat = (const float*)d_in[1];
        cent = (const float*)d_in[0];
    }

    cudaFuncSetAttribute((const void*)gemm_all,
                         cudaFuncAttributeMaxDynamicSharedMemorySize, SMEM_TOTAL);

    k_prep_feat<<<3072, 256>>>(feat);
    k_prep_cent<<<KK, 128>>>(cent);
    gemm_all<<<640, 256, SMEM_TOTAL>>>();
    k_finalj<<<JBLOCKS, 128>>>();
    k_reduce<<<1, 256>>>((float*)d_out);
}